// round 13
// baseline (speedup 1.0000x reference)
// R13: launch surgery — scanB folded into fill/gather (per-block smem prefix),
// g_pos zeroed in scanA, g_cnt zeroed in last hidden. gather is now kernel #4
// (the ncu-profiled slot). GEMM kernels identical to R12 (1128.7us baseline).
#include <cuda_runtime.h>
#include <math.h>

#define NN_NODES 100000
#define NN_EDGES 1600000
#define NRELS 4
#define DIMV 64
#define EPSV 1e-10f
#define NSEG (NN_NODES * NRELS)
#define SCAN_CHUNK 2048
#define NB1 ((NSEG + SCAN_CHUNK - 1) / SCAN_CHUNK)   // 196

// ---------------- scratch ----------------
__device__ int    g_cnt[NSEG];
__device__ int    g_off[NSEG];
__device__ int    g_pos[NSEG];
__device__ int    g_bsum[256];
__device__ float2 g_pack[NN_EDGES];                      // {.x = src bits, .y = weight}
__device__ float  g_upd[(size_t)NSEG * DIMV];            // normalized upd
__device__ float  g_buf[3][(size_t)NN_NODES * DIMV];     // hid0, hid1, gated

__device__ __forceinline__ float sigf(float v) { return 1.0f / (1.0f + expf(-v)); }

// ---------------- CSR build ----------------
__global__ void hist_kernel(const int* __restrict__ dst, const int* __restrict__ rel) {
    int e = blockIdx.x * blockDim.x + threadIdx.x;
    if (e < NN_EDGES) atomicAdd(&g_cnt[dst[e] * NRELS + rel[e]], 1);
}

__global__ __launch_bounds__(1024) void scanA_kernel() {
    __shared__ int sm[1024];
    int b = blockIdx.x, t = threadIdx.x;
    int i0 = b * SCAN_CHUNK + t * 2;
    int a0 = (i0 < NSEG) ? g_cnt[i0] : 0;
    int a1 = (i0 + 1 < NSEG) ? g_cnt[i0 + 1] : 0;
    int ts = a0 + a1;
    sm[t] = ts;
    // zero g_pos for this round (consumed by fill)
    if (i0 < NSEG) g_pos[i0] = 0;
    if (i0 + 1 < NSEG) g_pos[i0 + 1] = 0;
    __syncthreads();
    for (int off = 1; off < 1024; off <<= 1) {
        int v = (t >= off) ? sm[t - off] : 0;
        __syncthreads(); sm[t] += v; __syncthreads();
    }
    int ex = sm[t] - ts;
    if (i0 < NSEG) g_off[i0] = ex;
    if (i0 + 1 < NSEG) g_off[i0 + 1] = ex + a0;
    if (t == 1023) g_bsum[b] = sm[1023];
}

// per-block smem exclusive scan of g_bsum (196 entries) — replaces scanB
__device__ __forceinline__ void block_bscan(int* sbe) {
    __shared__ int sb[256];
    int t = threadIdx.x;
    int v = (t < NB1) ? g_bsum[t] : 0;
    sb[t] = v;
    __syncthreads();
    for (int off = 1; off < 256; off <<= 1) {
        int u = (t >= off) ? sb[t - off] : 0;
        __syncthreads(); sb[t] += u; __syncthreads();
    }
    sbe[t] = sb[t] - v;   // exclusive
    __syncthreads();
}

__global__ __launch_bounds__(256) void fill_kernel(
        const float* __restrict__ ew, const int* __restrict__ src,
        const int* __restrict__ dst, const int* __restrict__ rel) {
    __shared__ int sbe[256];
    block_bscan(sbe);
    int e = blockIdx.x * blockDim.x + threadIdx.x;
    if (e >= NN_EDGES) return;
    int seg = dst[e] * NRELS + rel[e];
    int p = atomicAdd(&g_pos[seg], 1);
    g_pack[g_off[seg] + sbe[seg >> 11] + p] = make_float2(__int_as_float(src[e]), ew[e]);
}

// ---------------- gather: 16 threads/segment, 4x unroll ----------------
__global__ __launch_bounds__(256) void gather_kernel(const float* __restrict__ x) {
    __shared__ int sbe[256];
    block_bscan(sbe);
    unsigned t = blockIdx.x * blockDim.x + threadIdx.x;
    unsigned seg = t >> 4;
    if (seg >= NSEG) return;
    int c = (t & 15) << 2;
    int st = g_off[seg] + sbe[seg >> 11];
    int cnt = g_cnt[seg];
    int en = st + cnt;
    float4 acc = make_float4(0.f, 0.f, 0.f, 0.f);
    float ws = 0.f;
    int i = st, en4 = st + (cnt & ~3);
    while (i < en4) {
        float2 p0 = __ldg(&g_pack[i]);
        float2 p1 = __ldg(&g_pack[i + 1]);
        float2 p2 = __ldg(&g_pack[i + 2]);
        float2 p3 = __ldg(&g_pack[i + 3]);
        int s0 = __float_as_int(p0.x), s1 = __float_as_int(p1.x);
        int s2 = __float_as_int(p2.x), s3 = __float_as_int(p3.x);
        float4 v0 = *(const float4*)(x + (size_t)s0 * DIMV + c);
        float4 v1 = *(const float4*)(x + (size_t)s1 * DIMV + c);
        float4 v2 = *(const float4*)(x + (size_t)s2 * DIMV + c);
        float4 v3 = *(const float4*)(x + (size_t)s3 * DIMV + c);
        acc.x += v0.x * p0.y + v1.x * p1.y + v2.x * p2.y + v3.x * p3.y;
        acc.y += v0.y * p0.y + v1.y * p1.y + v2.y * p2.y + v3.y * p3.y;
        acc.z += v0.z * p0.y + v1.z * p1.y + v2.z * p2.y + v3.z * p3.y;
        acc.w += v0.w * p0.y + v1.w * p1.y + v2.w * p2.y + v3.w * p3.y;
        ws += p0.y + p1.y + p2.y + p3.y;
        i += 4;
    }
    while (i < en) {
        float2 p = __ldg(&g_pack[i]);
        int s = __float_as_int(p.x);
        float4 v = *(const float4*)(x + (size_t)s * DIMV + c);
        acc.x += v.x * p.y; acc.y += v.y * p.y; acc.z += v.z * p.y; acc.w += v.w * p.y;
        ws += p.y; i++;
    }
    float inv = 1.0f / (ws + EPSV);
    *(float4*)&g_upd[(size_t)seg * DIMV + c] =
        make_float4(acc.x * inv, acc.y * inv, acc.z * inv, acc.w * inv);
}

// ---------------- 16-FFMA micro-tile ----------------
__device__ __forceinline__ void mm16(float (&acc)[4][4], float4 w, float4 in) {
    acc[0][0] += w.x * in.x; acc[0][1] += w.x * in.y; acc[0][2] += w.x * in.z; acc[0][3] += w.x * in.w;
    acc[1][0] += w.y * in.x; acc[1][1] += w.y * in.y; acc[1][2] += w.y * in.z; acc[1][3] += w.y * in.w;
    acc[2][0] += w.z * in.x; acc[2][1] += w.z * in.y; acc[2][2] += w.z * in.z; acc[2][3] += w.z * in.w;
    acc[3][0] += w.w * in.x; acc[3][1] += w.w * in.y; acc[3][2] += w.w * in.z; acc[3][3] += w.w * in.w;
}

// ---------------- hidden (R12-identical + g_cnt zeroing flag) ----------------
#define SMEM1_BYTES ((256*64 + 64*64 + 64*64 + 64*64) * 4)

__global__ __launch_bounds__(256, 2) void hidden_kernel(
    const float* __restrict__ x_in,
    const float* __restrict__ lin_w, const float* __restrict__ lin_b,
    const float* __restrict__ self_w, const float* __restrict__ self_b,
    float* __restrict__ hid_out, int zero_cnt) {
    extern __shared__ float sm[];
    float* w1  = sm;               // [256][64]
    float* w2  = w1 + 256 * 64;    // [64][64]
    float* upd = w2 + 64 * 64;     // [64][64] chunk, k-major
    float* xs  = upd + 64 * 64;    // [64][64]

    int tid = threadIdx.x;
    if (zero_cnt) {                // last layer: reset histogram for next graph replay
        int gi = blockIdx.x * 256 + tid;
        if (gi < NSEG) g_cnt[gi] = 0;
    }
    for (int i = tid * 4; i < 256 * 64; i += 1024)
        *(float4*)&w1[i] = *(const float4*)&lin_w[i];
    for (int i = tid * 4; i < 64 * 64; i += 1024)
        *(float4*)&w2[i] = *(const float4*)&self_w[i];

    int node0 = blockIdx.x * 64;

    int sn[4], sk[4], sgn[4];
#pragma unroll
    for (int j = 0; j < 4; j++) {
        int idx = tid + j * 256;
        sn[j] = idx & 63;
        sk[j] = (idx >> 6) << 2;
        sgn[j] = node0 + sn[j];
    }

    // x transposed load
#pragma unroll
    for (int j = 0; j < 4; j++) {
        float4 a = make_float4(0.f, 0.f, 0.f, 0.f);
        if (sgn[j] < NN_NODES)
            a = *(const float4*)&x_in[(size_t)sgn[j] * 64 + sk[j]];
        xs[(sk[j] + 0) * 64 + sn[j]] = a.x;
        xs[(sk[j] + 1) * 64 + sn[j]] = a.y;
        xs[(sk[j] + 2) * 64 + sn[j]] = a.z;
        xs[(sk[j] + 3) * 64 + sn[j]] = a.w;
    }

    // prefetch chunk 0
    float4 pf[4];
#pragma unroll
    for (int j = 0; j < 4; j++) {
        pf[j] = make_float4(0.f, 0.f, 0.f, 0.f);
        if (sgn[j] < NN_NODES)
            pf[j] = *(const float4*)&g_upd[(size_t)sgn[j] * 256 + sk[j]];
    }

    int j0 = (tid & 15) * 4;
    int n0 = (tid >> 4) * 4;
    float acc[4][4] = {};

    for (int kc = 0; kc < 4; kc++) {
        __syncthreads();
#pragma unroll
        for (int j = 0; j < 4; j++) {
            upd[(sk[j] + 0) * 64 + sn[j]] = pf[j].x;
            upd[(sk[j] + 1) * 64 + sn[j]] = pf[j].y;
            upd[(sk[j] + 2) * 64 + sn[j]] = pf[j].z;
            upd[(sk[j] + 3) * 64 + sn[j]] = pf[j].w;
        }
        __syncthreads();

        float4 nf[4];
        if (kc < 3) {
            int kbase = (kc + 1) * 64;
#pragma unroll
            for (int j = 0; j < 4; j++) {
                nf[j] = make_float4(0.f, 0.f, 0.f, 0.f);
                if (sgn[j] < NN_NODES)
                    nf[j] = *(const float4*)&g_upd[(size_t)sgn[j] * 256 + kbase + sk[j]];
            }
        } else {
#pragma unroll
            for (int j = 0; j < 4; j++) nf[j] = make_float4(0.f, 0.f, 0.f, 0.f);
        }

        const float* w1c = w1 + kc * 64 * 64;
#pragma unroll 8
        for (int k = 0; k < 64; k++) {
            float4 w = *(float4*)&w1c[k * 64 + j0];
            float4 in = *(float4*)&upd[k * 64 + n0];
            mm16(acc, w, in);
        }
#pragma unroll
        for (int j = 0; j < 4; j++) pf[j] = nf[j];
    }

#pragma unroll 8
    for (int k = 0; k < 64; k++) {
        float4 w = *(float4*)&w2[k * 64 + j0];
        float4 in = *(float4*)&xs[k * 64 + n0];
        mm16(acc, w, in);
    }

    float bj[4];
#pragma unroll
    for (int jj = 0; jj < 4; jj++)
        bj[jj] = __ldg(&lin_b[j0 + jj]) + __ldg(&self_b[j0 + jj]);

#pragma unroll
    for (int nn = 0; nn < 4; nn++) {
        int gn = node0 + n0 + nn;
        if (gn >= NN_NODES) continue;
        float4 o;
        o.x = sigf(acc[0][nn] + bj[0]);
        o.y = sigf(acc[1][nn] + bj[1]);
        o.z = sigf(acc[2][nn] + bj[2]);
        o.w = sigf(acc[3][nn] + bj[3]);
        *(float4*)&hid_out[(size_t)gn * 64 + j0] = o;
    }
}

// ---------------- highway (R12-identical) ----------------
#define SMEM2_BYTES ((128*64 + 128*64 + 128*64) * 4)

__global__ __launch_bounds__(256, 2) void highway_kernel(
    const float* __restrict__ hid, const float* __restrict__ prev,
    const float* __restrict__ pw, const float* __restrict__ pb,
    const float* __restrict__ tw, const float* __restrict__ tb,
    float* __restrict__ out) {
    extern __shared__ float sm[];
    float* pws = sm;
    float* tws = pws + 128 * 64;
    float* cat = tws + 128 * 64;

    int tid = threadIdx.x;
    for (int i = tid * 4; i < 128 * 64; i += 1024) {
        *(float4*)&pws[i] = *(const float4*)&pw[i];
        *(float4*)&tws[i] = *(const float4*)&tw[i];
    }

    int node0 = blockIdx.x * 64;
    for (int idx = tid; idx < 64 * 16; idx += 256) {
        int n = idx & 63;
        int k = (idx >> 6) << 2;
        int gn = node0 + n;
        float4 a = make_float4(0.f, 0.f, 0.f, 0.f);
        float4 b = make_float4(0.f, 0.f, 0.f, 0.f);
        if (gn < NN_NODES) {
            a = *(const float4*)&hid[(size_t)gn * 64 + k];
            b = *(const float4*)&prev[(size_t)gn * 64 + k];
        }
        cat[(k + 0) * 64 + n] = a.x;  cat[(64 + k + 0) * 64 + n] = b.x;
        cat[(k + 1) * 64 + n] = a.y;  cat[(64 + k + 1) * 64 + n] = b.y;
        cat[(k + 2) * 64 + n] = a.z;  cat[(64 + k + 2) * 64 + n] = b.z;
        cat[(k + 3) * 64 + n] = a.w;  cat[(64 + k + 3) * 64 + n] = b.w;
    }
    __syncthreads();

    int j0 = (tid & 15) * 4;
    int n0 = (tid >> 4) * 4;
    float accp[4][4] = {};
    float accg[4][4] = {};

#pragma unroll 8
    for (int k = 0; k < 128; k++) {
        float4 in = *(float4*)&cat[k * 64 + n0];
        float4 wp = *(float4*)&pws[k * 64 + j0];
        float4 wt = *(float4*)&tws[k * 64 + j0];
        mm16(accp, wp, in);
        mm16(accg, wt, in);
    }

    float pbj[4], tbj[4];
#pragma unroll
    for (int jj = 0; jj < 4; jj++) {
        pbj[jj] = __ldg(&pb[j0 + jj]);
        tbj[jj] = __ldg(&tb[j0 + jj]);
    }

#pragma unroll
    for (int nn = 0; nn < 4; nn++) {
        int gn = node0 + n0 + nn;
        if (gn >= NN_NODES) continue;
        float4 o;
#pragma unroll
        for (int jj = 0; jj < 4; jj++) {
            float p = fmaxf(accp[jj][nn] + pbj[jj], 0.0f);
            float g = sigf(accg[jj][nn] + tbj[jj]);
            float h = cat[(j0 + jj) * 64 + (n0 + nn)];
            ((float*)&o)[jj] = g * p + (1.0f - g) * h;
        }
        *(float4*)&out[(size_t)gn * 64 + j0] = o;
    }
}

// ---------------- host ----------------
extern "C" void kernel_launch(void* const* d_in, const int* in_sizes, int n_in,
                              void* d_out, int out_size) {
    const float* node_feat   = (const float*)d_in[0];
    const float* ew          = (const float*)d_in[1];
    const float* conv_lin_w  = (const float*)d_in[2];
    const float* conv_lin_b  = (const float*)d_in[3];
    const float* conv_self_w = (const float*)d_in[4];
    const float* conv_self_b = (const float*)d_in[5];
    const float* hw_proj_w   = (const float*)d_in[6];
    const float* hw_proj_b   = (const float*)d_in[7];
    const float* hw_trans_w  = (const float*)d_in[8];
    const float* hw_trans_b  = (const float*)d_in[9];
    const int*   src         = (const int*)d_in[10];
    const int*   dst         = (const int*)d_in[11];
    const int*   rel         = (const int*)d_in[12];
    float* out = (float*)d_out;

    void* buf_p = nullptr;
    cudaGetSymbolAddress(&buf_p, g_buf);
    float* hid0  = (float*)buf_p;
    float* hid1  = hid0 + (size_t)NN_NODES * DIMV;
    float* gated = hid1 + (size_t)NN_NODES * DIMV;
    float* hidv[2] = {hid0, hid1};

    cudaFuncSetAttribute(hidden_kernel, cudaFuncAttributeMaxDynamicSharedMemorySize, SMEM1_BYTES);
    cudaFuncSetAttribute(highway_kernel, cudaFuncAttributeMaxDynamicSharedMemorySize, SMEM2_BYTES);

    // CSR build: g_cnt zeroed by previous launch's last hidden (loader-zeroed on first call);
    // g_pos zeroed inside scanA.
    hist_kernel<<<(NN_EDGES + 255) / 256, 256>>>(dst, rel);            // #1
    scanA_kernel<<<NB1, 1024>>>();                                     // #2
    fill_kernel<<<(NN_EDGES + 255) / 256, 256>>>(ew, src, dst, rel);   // #3

    const float* x = node_feat;
    const float* prev = node_feat;
    int nblk = (NN_NODES + 63) / 64;

    for (int L = 0; L < 3; L++) {
        gather_kernel<<<(int)(((size_t)NSEG * 16 + 255) / 256), 256>>>(x);   // #4 on L=0 -> profiled

        float* hid = hidv[L & 1];
        hidden_kernel<<<nblk, 256, SMEM1_BYTES>>>(
            x,
            conv_lin_w + (size_t)L * 256 * 64, conv_lin_b + L * 64,
            conv_self_w + (size_t)L * 64 * 64, conv_self_b + L * 64,
            hid, (L == 2) ? 1 : 0);

        float* o = (L == 2) ? out : gated;
        highway_kernel<<<nblk, 256, SMEM2_BYTES>>>(
            hid, prev,
            hw_proj_w + (size_t)L * 128 * 64, hw_proj_b + L * 64,
            hw_trans_w + (size_t)L * 128 * 64, hw_trans_b + L * 64,
            o);

        x = o;
        prev = hid;
    }
}

// round 15
// speedup vs baseline: 1.1426x; 1.1426x over previous
// R15: byte-identical resubmission of R14 (broker infra flake, no kernel output).
// R12 structure + finalize kernel + packed fma.rn.f32x2 GEMM cores.
#include <cuda_runtime.h>
#include <math.h>
#include <stdint.h>

#define NN_NODES 100000
#define NN_EDGES 1600000
#define NRELS 4
#define DIMV 64
#define EPSV 1e-10f
#define NSEG (NN_NODES * NRELS)
#define SCAN_CHUNK 2048
#define NB1 ((NSEG + SCAN_CHUNK - 1) / SCAN_CHUNK)   // 196

// ---------------- scratch ----------------
__device__ int    g_cnt[NSEG];
__device__ int    g_off[NSEG];
__device__ int    g_pos[NSEG];
__device__ int    g_bsum[256];
__device__ float2 g_pack[NN_EDGES];                      // {.x = src bits, .y = weight}
__device__ float  g_upd[(size_t)NSEG * DIMV];            // normalized upd
__device__ float  g_buf[3][(size_t)NN_NODES * DIMV];     // hid0, hid1, gated

__device__ __forceinline__ float sigf(float v) { return 1.0f / (1.0f + expf(-v)); }

// ---------------- f32x2 packed-FMA primitives ----------------
__device__ __forceinline__ uint64_t pack2(float a, float b) {
    uint64_t r;
    asm("mov.b64 %0, {%1, %2};" : "=l"(r) : "f"(a), "f"(b));
    return r;
}
__device__ __forceinline__ void unpack2(uint64_t v, float& lo, float& hi) {
    asm("mov.b64 {%0, %1}, %2;" : "=f"(lo), "=f"(hi) : "l"(v));
}
__device__ __forceinline__ void fma2(uint64_t& d, uint64_t a, uint64_t b) {
    asm("fma.rn.f32x2 %0, %1, %2, %0;" : "+l"(d) : "l"(a), "l"(b));
}

// ---------------- CSR build ----------------
__global__ void hist_kernel(const int* __restrict__ dst, const int* __restrict__ rel) {
    int e = blockIdx.x * blockDim.x + threadIdx.x;
    if (e < NN_EDGES) atomicAdd(&g_cnt[dst[e] * NRELS + rel[e]], 1);
}

__global__ __launch_bounds__(1024) void scanA_kernel() {
    __shared__ int sm[1024];
    int b = blockIdx.x, t = threadIdx.x;
    int i0 = b * SCAN_CHUNK + t * 2;
    int a0 = (i0 < NSEG) ? g_cnt[i0] : 0;
    int a1 = (i0 + 1 < NSEG) ? g_cnt[i0 + 1] : 0;
    int ts = a0 + a1;
    sm[t] = ts;
    if (i0 < NSEG) g_pos[i0] = 0;             // zero g_pos for fill
    if (i0 + 1 < NSEG) g_pos[i0 + 1] = 0;
    __syncthreads();
    for (int off = 1; off < 1024; off <<= 1) {
        int v = (t >= off) ? sm[t - off] : 0;
        __syncthreads(); sm[t] += v; __syncthreads();
    }
    int ex = sm[t] - ts;
    if (i0 < NSEG) g_off[i0] = ex;
    if (i0 + 1 < NSEG) g_off[i0 + 1] = ex + a0;
    if (t == 1023) g_bsum[b] = sm[1023];
}

// finalize: one pass adding cross-block prefix into g_off (bscan recomputed in smem)
__global__ __launch_bounds__(256) void finalize_kernel() {
    __shared__ int sb[256];
    int t = threadIdx.x;
    int v = (t < NB1) ? g_bsum[t] : 0;
    sb[t] = v;
    __syncthreads();
    for (int off = 1; off < 256; off <<= 1) {
        int u = (t >= off) ? sb[t - off] : 0;
        __syncthreads(); sb[t] += u; __syncthreads();
    }
    __shared__ int sbe[256];
    sbe[t] = sb[t] - v;
    __syncthreads();
    int i = blockIdx.x * 256 + t;
    if (i < NSEG) g_off[i] += sbe[i >> 11];
}

__global__ void fill_kernel(const float* __restrict__ ew, const int* __restrict__ src,
                            const int* __restrict__ dst, const int* __restrict__ rel) {
    int e = blockIdx.x * blockDim.x + threadIdx.x;
    if (e >= NN_EDGES) return;
    int seg = dst[e] * NRELS + rel[e];
    int p = atomicAdd(&g_pos[seg], 1);
    g_pack[g_off[seg] + p] = make_float2(__int_as_float(src[e]), ew[e]);
}

// ---------------- gather: 16 threads/segment, 4x unroll (R12-identical) ----------------
__global__ __launch_bounds__(256) void gather_kernel(const float* __restrict__ x) {
    unsigned t = blockIdx.x * blockDim.x + threadIdx.x;
    unsigned seg = t >> 4;
    if (seg >= NSEG) return;
    int c = (t & 15) << 2;
    int st = g_off[seg];
    int cnt = g_cnt[seg];
    int en = st + cnt;
    float4 acc = make_float4(0.f, 0.f, 0.f, 0.f);
    float ws = 0.f;
    int i = st, en4 = st + (cnt & ~3);
    while (i < en4) {
        float2 p0 = __ldg(&g_pack[i]);
        float2 p1 = __ldg(&g_pack[i + 1]);
        float2 p2 = __ldg(&g_pack[i + 2]);
        float2 p3 = __ldg(&g_pack[i + 3]);
        int s0 = __float_as_int(p0.x), s1 = __float_as_int(p1.x);
        int s2 = __float_as_int(p2.x), s3 = __float_as_int(p3.x);
        float4 v0 = *(const float4*)(x + (size_t)s0 * DIMV + c);
        float4 v1 = *(const float4*)(x + (size_t)s1 * DIMV + c);
        float4 v2 = *(const float4*)(x + (size_t)s2 * DIMV + c);
        float4 v3 = *(const float4*)(x + (size_t)s3 * DIMV + c);
        acc.x += v0.x * p0.y + v1.x * p1.y + v2.x * p2.y + v3.x * p3.y;
        acc.y += v0.y * p0.y + v1.y * p1.y + v2.y * p2.y + v3.y * p3.y;
        acc.z += v0.z * p0.y + v1.z * p1.y + v2.z * p2.y + v3.z * p3.y;
        acc.w += v0.w * p0.y + v1.w * p1.y + v2.w * p2.y + v3.w * p3.y;
        ws += p0.y + p1.y + p2.y + p3.y;
        i += 4;
    }
    while (i < en) {
        float2 p = __ldg(&g_pack[i]);
        int s = __float_as_int(p.x);
        float4 v = *(const float4*)(x + (size_t)s * DIMV + c);
        acc.x += v.x * p.y; acc.y += v.y * p.y; acc.z += v.z * p.y; acc.w += v.w * p.y;
        ws += p.y; i++;
    }
    float inv = 1.0f / (ws + EPSV);
    *(float4*)&g_upd[(size_t)seg * DIMV + c] =
        make_float4(acc.x * inv, acc.y * inv, acc.z * inv, acc.w * inv);
}

// ---------------- packed 16-MAC micro-tile: 8 FMA2 + 4 dups ----------------
// acc01[n] = (acc[j0][n], acc[j0+1][n]); acc23[n] = (acc[j0+2][n], acc[j0+3][n])
__device__ __forceinline__ void mm16p(uint64_t (&a01)[4], uint64_t (&a23)[4],
                                      const float* wrow, float4 in) {
    uint64_t w01 = *(const uint64_t*)wrow;
    uint64_t w23 = *(const uint64_t*)(wrow + 2);
    uint64_t d0 = pack2(in.x, in.x);
    uint64_t d1 = pack2(in.y, in.y);
    uint64_t d2 = pack2(in.z, in.z);
    uint64_t d3 = pack2(in.w, in.w);
    fma2(a01[0], w01, d0); fma2(a23[0], w23, d0);
    fma2(a01[1], w01, d1); fma2(a23[1], w23, d1);
    fma2(a01[2], w01, d2); fma2(a23[2], w23, d2);
    fma2(a01[3], w01, d3); fma2(a23[3], w23, d3);
}

// ---------------- hidden = sigmoid(upd@lin_w + x@self_w + b) ----------------
// Smem 112KB -> 2 blocks/SM; register double-buffered g_upd staging (R12-proven).
#define SMEM1_BYTES ((256*64 + 64*64 + 64*64 + 64*64) * 4)

__global__ __launch_bounds__(256, 2) void hidden_kernel(
    const float* __restrict__ x_in,
    const float* __restrict__ lin_w, const float* __restrict__ lin_b,
    const float* __restrict__ self_w, const float* __restrict__ self_b,
    float* __restrict__ hid_out, int zero_cnt) {
    extern __shared__ float sm[];
    float* w1  = sm;               // [256][64]
    float* w2  = w1 + 256 * 64;    // [64][64]
    float* upd = w2 + 64 * 64;     // [64][64] chunk, k-major
    float* xs  = upd + 64 * 64;    // [64][64]

    int tid = threadIdx.x;
    if (zero_cnt) {
        int gi = blockIdx.x * 256 + tid;
        if (gi < NSEG) g_cnt[gi] = 0;
    }
    for (int i = tid * 4; i < 256 * 64; i += 1024)
        *(float4*)&w1[i] = *(const float4*)&lin_w[i];
    for (int i = tid * 4; i < 64 * 64; i += 1024)
        *(float4*)&w2[i] = *(const float4*)&self_w[i];

    int node0 = blockIdx.x * 64;

    int sn[4], sk[4], sgn[4];
#pragma unroll
    for (int j = 0; j < 4; j++) {
        int idx = tid + j * 256;
        sn[j] = idx & 63;
        sk[j] = (idx >> 6) << 2;
        sgn[j] = node0 + sn[j];
    }

    // x transposed load
#pragma unroll
    for (int j = 0; j < 4; j++) {
        float4 a = make_float4(0.f, 0.f, 0.f, 0.f);
        if (sgn[j] < NN_NODES)
            a = *(const float4*)&x_in[(size_t)sgn[j] * 64 + sk[j]];
        xs[(sk[j] + 0) * 64 + sn[j]] = a.x;
        xs[(sk[j] + 1) * 64 + sn[j]] = a.y;
        xs[(sk[j] + 2) * 64 + sn[j]] = a.z;
        xs[(sk[j] + 3) * 64 + sn[j]] = a.w;
    }

    // prefetch chunk 0
    float4 pf[4];
#pragma unroll
    for (int j = 0; j < 4; j++) {
        pf[j] = make_float4(0.f, 0.f, 0.f, 0.f);
        if (sgn[j] < NN_NODES)
            pf[j] = *(const float4*)&g_upd[(size_t)sgn[j] * 256 + sk[j]];
    }

    int j0 = (tid & 15) * 4;
    int n0 = (tid >> 4) * 4;
    uint64_t a01[4] = {0, 0, 0, 0};
    uint64_t a23[4] = {0, 0, 0, 0};

    for (int kc = 0; kc < 4; kc++) {
        __syncthreads();
#pragma unroll
        for (int j = 0; j < 4; j++) {
            upd[(sk[j] + 0) * 64 + sn[j]] = pf[j].x;
            upd[(sk[j] + 1) * 64 + sn[j]] = pf[j].y;
            upd[(sk[j] + 2) * 64 + sn[j]] = pf[j].z;
            upd[(sk[j] + 3) * 64 + sn[j]] = pf[j].w;
        }
        __syncthreads();

        float4 nf[4];
        if (kc < 3) {
            int kbase = (kc + 1) * 64;
#pragma unroll
            for (int j = 0; j < 4; j++) {
                nf[j] = make_float4(0.f, 0.f, 0.f, 0.f);
                if (sgn[j] < NN_NODES)
                    nf[j] = *(const float4*)&g_upd[(size_t)sgn[j] * 256 + kbase + sk[j]];
            }
        } else {
#pragma unroll
            for (int j = 0; j < 4; j++) nf[j] = make_float4(0.f, 0.f, 0.f, 0.f);
        }

        const float* w1c = w1 + kc * 64 * 64;
#pragma unroll 8
        for (int k = 0; k < 64; k++) {
            float4 in = *(float4*)&upd[k * 64 + n0];
            mm16p(a01, a23, &w1c[k * 64 + j0], in);
        }
#pragma unroll
        for (int j = 0; j < 4; j++) pf[j] = nf[j];
    }

#pragma unroll 8
    for (int k = 0; k < 64; k++) {
        float4 in = *(float4*)&xs[k * 64 + n0];
        mm16p(a01, a23, &w2[k * 64 + j0], in);
    }

    float bj[4];
#pragma unroll
    for (int jj = 0; jj < 4; jj++)
        bj[jj] = __ldg(&lin_b[j0 + jj]) + __ldg(&self_b[j0 + jj]);

#pragma unroll
    for (int nn = 0; nn < 4; nn++) {
        int gn = node0 + n0 + nn;
        if (gn >= NN_NODES) continue;
        float v0, v1, v2, v3;
        unpack2(a01[nn], v0, v1);
        unpack2(a23[nn], v2, v3);
        float4 o;
        o.x = sigf(v0 + bj[0]);
        o.y = sigf(v1 + bj[1]);
        o.z = sigf(v2 + bj[2]);
        o.w = sigf(v3 + bj[3]);
        *(float4*)&hid_out[(size_t)gn * 64 + j0] = o;
    }
}

// ---------------- highway: gate*relu(proj) + (1-gate)*hidden ----------------
#define SMEM2_BYTES ((128*64 + 128*64 + 128*64) * 4)

__global__ __launch_bounds__(256, 2) void highway_kernel(
    const float* __restrict__ hid, const float* __restrict__ prev,
    const float* __restrict__ pw, const float* __restrict__ pb,
    const float* __restrict__ tw, const float* __restrict__ tb,
    float* __restrict__ out) {
    extern __shared__ float sm[];
    float* pws = sm;
    float* tws = pws + 128 * 64;
    float* cat = tws + 128 * 64;

    int tid = threadIdx.x;
    for (int i = tid * 4; i < 128 * 64; i += 1024) {
        *(float4*)&pws[i] = *(const float4*)&pw[i];
        *(float4*)&tws[i] = *(const float4*)&tw[i];
    }

    int node0 = blockIdx.x * 64;
    for (int idx = tid; idx < 64 * 16; idx += 256) {
        int n = idx & 63;
        int k = (idx >> 6) << 2;
        int gn = node0 + n;
        float4 a = make_float4(0.f, 0.f, 0.f, 0.f);
        float4 b = make_float4(0.f, 0.f, 0.f, 0.f);
        if (gn < NN_NODES) {
            a = *(const float4*)&hid[(size_t)gn * 64 + k];
            b = *(const float4*)&prev[(size_t)gn * 64 + k];
        }
        cat[(k + 0) * 64 + n] = a.x;  cat[(64 + k + 0) * 64 + n] = b.x;
        cat[(k + 1) * 64 + n] = a.y;  cat[(64 + k + 1) * 64 + n] = b.y;
        cat[(k + 2) * 64 + n] = a.z;  cat[(64 + k + 2) * 64 + n] = b.z;
        cat[(k + 3) * 64 + n] = a.w;  cat[(64 + k + 3) * 64 + n] = b.w;
    }
    __syncthreads();

    int j0 = (tid & 15) * 4;
    int n0 = (tid >> 4) * 4;
    uint64_t p01[4] = {0, 0, 0, 0};
    uint64_t p23[4] = {0, 0, 0, 0};
    uint64_t t01[4] = {0, 0, 0, 0};
    uint64_t t23[4] = {0, 0, 0, 0};

#pragma unroll 8
    for (int k = 0; k < 128; k++) {
        float4 in = *(float4*)&cat[k * 64 + n0];
        mm16p(p01, p23, &pws[k * 64 + j0], in);
        mm16p(t01, t23, &tws[k * 64 + j0], in);
    }

    float pbj[4], tbj[4];
#pragma unroll
    for (int jj = 0; jj < 4; jj++) {
        pbj[jj] = __ldg(&pb[j0 + jj]);
        tbj[jj] = __ldg(&tb[j0 + jj]);
    }

#pragma unroll
    for (int nn = 0; nn < 4; nn++) {
        int gn = node0 + n0 + nn;
        if (gn >= NN_NODES) continue;
        float pv[4], tv[4];
        unpack2(p01[nn], pv[0], pv[1]);
        unpack2(p23[nn], pv[2], pv[3]);
        unpack2(t01[nn], tv[0], tv[1]);
        unpack2(t23[nn], tv[2], tv[3]);
        float4 o;
#pragma unroll
        for (int jj = 0; jj < 4; jj++) {
            float p = fmaxf(pv[jj] + pbj[jj], 0.0f);
            float g = sigf(tv[jj] + tbj[jj]);
            float h = cat[(j0 + jj) * 64 + (n0 + nn)];
            ((float*)&o)[jj] = g * p + (1.0f - g) * h;
        }
        *(float4*)&out[(size_t)gn * 64 + j0] = o;
    }
}

// ---------------- host ----------------
extern "C" void kernel_launch(void* const* d_in, const int* in_sizes, int n_in,
                              void* d_out, int out_size) {
    const float* node_feat   = (const float*)d_in[0];
    const float* ew          = (const float*)d_in[1];
    const float* conv_lin_w  = (const float*)d_in[2];
    const float* conv_lin_b  = (const float*)d_in[3];
    const float* conv_self_w = (const float*)d_in[4];
    const float* conv_self_b = (const float*)d_in[5];
    const float* hw_proj_w   = (const float*)d_in[6];
    const float* hw_proj_b   = (const float*)d_in[7];
    const float* hw_trans_w  = (const float*)d_in[8];
    const float* hw_trans_b  = (const float*)d_in[9];
    const int*   src         = (const int*)d_in[10];
    const int*   dst         = (const int*)d_in[11];
    const int*   rel         = (const int*)d_in[12];
    float* out = (float*)d_out;

    void* buf_p = nullptr;
    cudaGetSymbolAddress(&buf_p, g_buf);
    float* hid0  = (float*)buf_p;
    float* hid1  = hid0 + (size_t)NN_NODES * DIMV;
    float* gated = hid1 + (size_t)NN_NODES * DIMV;
    float* hidv[2] = {hid0, hid1};

    cudaFuncSetAttribute(hidden_kernel, cudaFuncAttributeMaxDynamicSharedMemorySize, SMEM1_BYTES);
    cudaFuncSetAttribute(highway_kernel, cudaFuncAttributeMaxDynamicSharedMemorySize, SMEM2_BYTES);

    // CSR build: g_cnt zeroed by previous launch's last hidden (loader-zeroed first call);
    // g_pos zeroed inside scanA; finalize folds cross-block prefix into g_off.
    hist_kernel<<<(NN_EDGES + 255) / 256, 256>>>(dst, rel);            // #1
    scanA_kernel<<<NB1, 1024>>>();                                     // #2
    finalize_kernel<<<(NSEG + 255) / 256, 256>>>();                    // #3
    fill_kernel<<<(NN_EDGES + 255) / 256, 256>>>(ew, src, dst, rel);   // #4 (profiled)

    const float* x = node_feat;
    const float* prev = node_feat;
    int nblk = (NN_NODES + 63) / 64;

    for (int L = 0; L < 3; L++) {
        gather_kernel<<<(int)(((size_t)NSEG * 16 + 255) / 256), 256>>>(x);

        float* hid = hidv[L & 1];
        hidden_kernel<<<nblk, 256, SMEM1_BYTES>>>(
            x,
            conv_lin_w + (size_t)L * 256 * 64, conv_lin_b + L * 64,
            conv_self_w + (size_t)L * 64 * 64, conv_self_b + L * 64,
            hid, (L == 2) ? 1 : 0);

        float* o = (L == 2) ? out : gated;
        highway_kernel<<<nblk, 256, SMEM2_BYTES>>>(
            hid, prev,
            hw_proj_w + (size_t)L * 128 * 64, hw_proj_b + L * 64,
            hw_trans_w + (size_t)L * 128 * 64, hw_trans_b + L * 64,
            o);

        x = o;
        prev = hid;
    }
}